// round 5
// baseline (speedup 1.0000x reference)
#include <cuda_runtime.h>

// BatteryRNNCell, R5:
//  - build kernel: 1 MLP eval/thread, neighbor delta via smem (was 2 evals/thread)
//  - main kernel: 2 elements/thread for memory-level parallelism (regs ~55, occ ~60%)

#define DEVI __device__ __forceinline__

#define R_CONST    8.3144621f
#define F_CONST    96487.0f
#define KN_C       20000.0f
#define VOL_C      2.2e-05f
#define VOLS_C     (0.1f * VOL_C)
#define VOLB_C     (VOL_C - VOLS_C)
#define U0P_C      4.03f
#define U0N_C      0.01f

#define TAB_N 4096
#define THREADS 256
#define EPT 2   // elements per thread in main kernel

// Scratch: MLP lookup table. tab[i] = (f(x_i), f(x_{i+1}) - f(x_i)), x_i = i/TAB_N.
__device__ float2 g_mlp_tab[TAB_N];

DEVI float fast_tanh(float x) {
    float e = __expf(2.0f * x);
    return 1.0f - __fdividef(2.0f, e + 1.0f);
}

DEVI float clampf(float v, float lo, float hi) {
    return fminf(fmaxf(v, lo), hi);
}

DEVI float mlp_eval(float x,
                    const float* __restrict__ Wp0, const float* __restrict__ bp0,
                    const float* __restrict__ Wp2, const float* __restrict__ bp2,
                    const float* __restrict__ Wp4, const float* __restrict__ bp4) {
    float h[8];
    #pragma unroll
    for (int j = 0; j < 8; j++)
        h[j] = fast_tanh(fmaf(__ldg(&Wp0[j]), x, __ldg(&bp0[j])));
    float out = __ldg(&bp4[0]);
    #pragma unroll
    for (int k = 0; k < 4; k++) {
        float a = __ldg(&bp2[k]);
        #pragma unroll
        for (int j = 0; j < 8; j++)
            a = fmaf(__ldg(&Wp2[k * 8 + j]), h[j], a);
        out = fmaf(__ldg(&Wp4[k]), fast_tanh(a), out);
    }
    return out;
}

__global__ void build_mlp_table(
    const float* __restrict__ Wp0, const float* __restrict__ bp0,
    const float* __restrict__ Wp2, const float* __restrict__ bp2,
    const float* __restrict__ Wp4, const float* __restrict__ bp4) {
    __shared__ float sf[THREADS + 1];
    int tid = threadIdx.x;
    int i = blockIdx.x * THREADS + tid;   // entry index, i < TAB_N
    const float inv = 1.0f / (float)TAB_N;

    sf[tid] = mlp_eval((float)i * inv, Wp0, bp0, Wp2, bp2, Wp4, bp4);
    if (tid == 0) {
        // block-boundary value f(x_{blockEnd})
        int j = blockIdx.x * THREADS + THREADS;
        sf[THREADS] = mlp_eval((float)j * inv, Wp0, bp0, Wp2, bp2, Wp4, bp4);
    }
    __syncthreads();
    g_mlp_tab[i] = make_float2(sf[tid], sf[tid + 1] - sf[tid]);
}

__global__ void __launch_bounds__(THREADS) battery_cell_kernel(
    const float* __restrict__ inputs,
    const float* __restrict__ states,
    const float* __restrict__ qMax,
    const float* __restrict__ Ro,
    const float* __restrict__ Wn,  const float* __restrict__ bn,
    float* __restrict__ outV, float* __restrict__ outX, int n)
{
    const int base = blockIdx.x * (THREADS * EPT) + threadIdx.x;
    const float4* st4 = reinterpret_cast<const float4*>(states);
    float4* ox4 = reinterpret_cast<float4*>(outX);

    const float w_n = __ldg(&Wn[0]);
    const float b_n = __ldg(&bn[0]);

    // ---- front-batched loads for both elements (MLP) ----
    float4 s0[EPT], s1[EPT];
    float iv[EPT], qMv[EPT], rov[EPT];
    bool valid[EPT];
    #pragma unroll
    for (int k = 0; k < EPT; k++) {
        int b = base + k * THREADS;
        valid[k] = (b < n);
        if (valid[k]) {
            s0[k] = st4[2 * b];
            s1[k] = st4[2 * b + 1];
            iv[k] = inputs[b];
            qMv[k] = qMax[b];
            rov[k] = Ro[b];
        }
    }

    #pragma unroll
    for (int k = 0; k < EPT; k++) {
        if (!valid[k]) continue;
        int b = base + k * THREADS;

        float Tb = s0[k].x, Vo = s0[k].y, Vsn = s0[k].z, Vsp = s0[k].w;
        float qnB = s1[k].x, qnS = s1[k].y, qpB = s1[k].z, qpS = s1[k].w;
        float i = iv[k];

        float inv_qSMax = __fdividef(1.0f, qMv[k] * 1000.0f);

        // ---- getNextState ----
        float xpS = clampf(qpS * inv_qSMax, 1e-18f, 1.0f);
        float xnS = clampf(qnS * inv_qSMax, 1e-18f, 1.0f);
        float Jn0 = 1e-18f + KN_C * sqrtf(xnS - xnS * xnS);
        float Jp0 = 1e-18f + KN_C * sqrtf(xpS - xpS * xpS);

        const float cB = 1.0f / (VOLB_C * 7.0e6f);
        const float cS = 1.0f / (VOLS_C * 7.0e6f);
        float qdn = qnB * cB - qnS * cS;
        float qdp = qpB * cB - qpS * cS;

        float J = i * 5000.0f;

        float VoNom  = i * rov[k] * 10.0f;
        const float C1 = R_CONST / F_CONST / 0.5f;
        float un = __fdividef(J, 2.0f * Jn0);
        float up = __fdividef(J, 2.0f * Jp0);
        float VsnNom = C1 * Tb * __logf(un + sqrtf(fmaf(un, un, 1.0f)));
        float VspNom = C1 * Tb * __logf(up + sqrtf(fmaf(up, up, 1.0f)));

        float Tb2  = Tb;
        float Vo2  = Vo  + (VoNom  - Vo ) * (1.0f / 10.0f);
        float Vsn2 = Vsn + (VsnNom - Vsn) * (1.0f / 90.0f);
        float Vsp2 = Vsp + (VspNom - Vsp) * (1.0f / 90.0f);
        float qnB2 = qnB - qdn;
        float qnS2 = qnS + qdn - i;
        float qpB2 = qpB - qdp;
        float qpS2 = qpS + i + qdp;

        // ---- getNextOutput ----
        float xpo = qpS2 * inv_qSMax;
        float xno = qnS2 * inv_qSMax;

        float t = xpo * (float)TAB_N;
        float fi = floorf(t);
        int idx = min(max((int)fi, 0), TAB_N - 1);
        float2 tv = __ldg(&g_mlp_tab[idx]);
        float VepMLP = fmaf(tv.y, t - (float)idx, tv.x);

        float VenMLP = fmaf(xno, w_n, b_n);

        float ratio_p = clampf(__fdividef(1.0f - xpo, xpo), 1e-18f, 1e18f);
        float ratio_n = clampf(__fdividef(1.0f - xno, xno), 1e-18f, 1e18f);
        const float C2 = R_CONST / F_CONST;
        float Vep = U0P_C + C2 * Tb2 * __logf(ratio_p) + VepMLP;
        float Ven = U0N_C + C2 * Tb2 * __logf(ratio_n) + VenMLP;

        float V = Vep - Ven - Vo2 - Vsn2 - Vsp2;

        outV[b] = V;
        ox4[2 * b]     = make_float4(Tb2, Vo2, Vsn2, Vsp2);
        ox4[2 * b + 1] = make_float4(qnB2, qnS2, qpB2, qpS2);
    }
}

extern "C" void kernel_launch(void* const* d_in, const int* in_sizes, int n_in,
                              void* d_out, int out_size) {
    const float* inputs = (const float*)d_in[0];
    const float* states = (const float*)d_in[1];
    const float* qMax   = (const float*)d_in[2];
    const float* Ro     = (const float*)d_in[3];
    const float* Wp0    = (const float*)d_in[4];
    const float* bp0    = (const float*)d_in[5];
    const float* Wp2    = (const float*)d_in[6];
    const float* bp2    = (const float*)d_in[7];
    const float* Wp4    = (const float*)d_in[8];
    const float* bp4    = (const float*)d_in[9];
    const float* Wn     = (const float*)d_in[10];
    const float* bn     = (const float*)d_in[11];

    int n = in_sizes[0];  // B
    float* outV = (float*)d_out;
    float* outX = outV + n;

    build_mlp_table<<<TAB_N / THREADS, THREADS>>>(Wp0, bp0, Wp2, bp2, Wp4, bp4);

    int elems_per_block = THREADS * EPT;
    int blocks = (n + elems_per_block - 1) / elems_per_block;
    battery_cell_kernel<<<blocks, THREADS>>>(
        inputs, states, qMax, Ro, Wn, bn, outV, outX, n);
}

// round 6
// speedup vs baseline: 1.0213x; 1.0213x over previous
#include <cuda_runtime.h>

// BatteryRNNCell, R6:
//  - main kernel = R4 config (EPT=1, 32 regs, occ ~80%)
//  - build kernel overlapped with main kernel via Programmatic Dependent Launch:
//    main kernel does all table-independent work (state update + XNew stores),
//    then cudaGridDependencySynchronize() right before the single table read.

#define DEVI __device__ __forceinline__

#define R_CONST    8.3144621f
#define F_CONST    96487.0f
#define KN_C       20000.0f
#define VOL_C      2.2e-05f
#define VOLS_C     (0.1f * VOL_C)
#define VOLB_C     (VOL_C - VOLS_C)
#define U0P_C      4.03f
#define U0N_C      0.01f

#define TAB_N 4096
#define THREADS 256

// Scratch: MLP lookup table. tab[i] = (f(x_i), f(x_{i+1}) - f(x_i)), x_i = i/TAB_N.
__device__ float2 g_mlp_tab[TAB_N];

DEVI float fast_tanh(float x) {
    float e = __expf(2.0f * x);
    return 1.0f - __fdividef(2.0f, e + 1.0f);
}

DEVI float clampf(float v, float lo, float hi) {
    return fminf(fmaxf(v, lo), hi);
}

DEVI float mlp_eval(float x,
                    const float* __restrict__ Wp0, const float* __restrict__ bp0,
                    const float* __restrict__ Wp2, const float* __restrict__ bp2,
                    const float* __restrict__ Wp4, const float* __restrict__ bp4) {
    float h[8];
    #pragma unroll
    for (int j = 0; j < 8; j++)
        h[j] = fast_tanh(fmaf(__ldg(&Wp0[j]), x, __ldg(&bp0[j])));
    float out = __ldg(&bp4[0]);
    #pragma unroll
    for (int k = 0; k < 4; k++) {
        float a = __ldg(&bp2[k]);
        #pragma unroll
        for (int j = 0; j < 8; j++)
            a = fmaf(__ldg(&Wp2[k * 8 + j]), h[j], a);
        out = fmaf(__ldg(&Wp4[k]), fast_tanh(a), out);
    }
    return out;
}

__global__ void build_mlp_table(
    const float* __restrict__ Wp0, const float* __restrict__ bp0,
    const float* __restrict__ Wp2, const float* __restrict__ bp2,
    const float* __restrict__ Wp4, const float* __restrict__ bp4) {
    __shared__ float sf[THREADS + 1];
    int tid = threadIdx.x;
    int i = blockIdx.x * THREADS + tid;
    const float inv = 1.0f / (float)TAB_N;

    sf[tid] = mlp_eval((float)i * inv, Wp0, bp0, Wp2, bp2, Wp4, bp4);
    if (tid == 0) {
        int j = blockIdx.x * THREADS + THREADS;
        sf[THREADS] = mlp_eval((float)j * inv, Wp0, bp0, Wp2, bp2, Wp4, bp4);
    }
    __syncthreads();
    g_mlp_tab[i] = make_float2(sf[tid], sf[tid + 1] - sf[tid]);
}

__global__ void __launch_bounds__(THREADS) battery_cell_kernel(
    const float* __restrict__ inputs,
    const float* __restrict__ states,
    const float* __restrict__ qMax,
    const float* __restrict__ Ro,
    const float* __restrict__ Wn,  const float* __restrict__ bn,
    float* __restrict__ outV, float* __restrict__ outX, int n)
{
    int b = blockIdx.x * blockDim.x + threadIdx.x;
    if (b >= n) {
#if __CUDA_ARCH__ >= 900
        cudaGridDependencySynchronize();
#endif
        return;
    }

    // ---- coalesced per-element loads (independent of the table build) ----
    const float4* st4 = reinterpret_cast<const float4*>(states);
    float4 s0 = st4[2 * b];       // Tb, Vo, Vsn, Vsp
    float4 s1 = st4[2 * b + 1];   // qnB, qnS, qpB, qpS
    float i   = inputs[b];
    float qM  = qMax[b];
    float ro  = Ro[b];

    float Tb = s0.x, Vo = s0.y, Vsn = s0.z, Vsp = s0.w;
    float qnB = s1.x, qnS = s1.y, qpB = s1.z, qpS = s1.w;

    float inv_qSMax = __fdividef(1.0f, qM * 1000.0f);

    // ---- getNextState ----
    float xpS = clampf(qpS * inv_qSMax, 1e-18f, 1.0f);
    float xnS = clampf(qnS * inv_qSMax, 1e-18f, 1.0f);
    float Jn0 = 1e-18f + KN_C * sqrtf(xnS - xnS * xnS);
    float Jp0 = 1e-18f + KN_C * sqrtf(xpS - xpS * xpS);

    const float cB = 1.0f / (VOLB_C * 7.0e6f);
    const float cS = 1.0f / (VOLS_C * 7.0e6f);
    float qdn = qnB * cB - qnS * cS;
    float qdp = qpB * cB - qpS * cS;

    float J = i * 5000.0f;

    float VoNom  = i * ro * 10.0f;
    const float C1 = R_CONST / F_CONST / 0.5f;
    float un = __fdividef(J, 2.0f * Jn0);
    float up = __fdividef(J, 2.0f * Jp0);
    float VsnNom = C1 * Tb * __logf(un + sqrtf(fmaf(un, un, 1.0f)));
    float VspNom = C1 * Tb * __logf(up + sqrtf(fmaf(up, up, 1.0f)));

    float Tb2  = Tb;
    float Vo2  = Vo  + (VoNom  - Vo ) * (1.0f / 10.0f);
    float Vsn2 = Vsn + (VsnNom - Vsn) * (1.0f / 90.0f);
    float Vsp2 = Vsp + (VspNom - Vsp) * (1.0f / 90.0f);
    float qnB2 = qnB - qdn;
    float qnS2 = qnS + qdn - i;
    float qpB2 = qpB - qdp;
    float qpS2 = qpS + i + qdp;

    // ---- table-independent output math + XNew stores ----
    float xpo = qpS2 * inv_qSMax;
    float xno = qnS2 * inv_qSMax;

    float VenMLP = fmaf(xno, __ldg(&Wn[0]), __ldg(&bn[0]));

    float ratio_p = clampf(__fdividef(1.0f - xpo, xpo), 1e-18f, 1e18f);
    float ratio_n = clampf(__fdividef(1.0f - xno, xno), 1e-18f, 1e18f);
    const float C2 = R_CONST / F_CONST;
    float Vep_part = U0P_C + C2 * Tb2 * __logf(ratio_p);      // + VepMLP later
    float Ven      = U0N_C + C2 * Tb2 * __logf(ratio_n) + VenMLP;

    float4* ox4 = reinterpret_cast<float4*>(outX);
    ox4[2 * b]     = make_float4(Tb2, Vo2, Vsn2, Vsp2);
    ox4[2 * b + 1] = make_float4(qnB2, qnS2, qpB2, qpS2);

    // ---- wait for the table builder, then the single dependent read ----
#if __CUDA_ARCH__ >= 900
    cudaGridDependencySynchronize();
#endif

    float t = xpo * (float)TAB_N;
    int idx = min(max(__float2int_rd(t), 0), TAB_N - 1);
    float2 tv = __ldg(&g_mlp_tab[idx]);
    float VepMLP = fmaf(tv.y, t - (float)idx, tv.x);

    outV[b] = (Vep_part + VepMLP) - Ven - Vo2 - Vsn2 - Vsp2;
}

extern "C" void kernel_launch(void* const* d_in, const int* in_sizes, int n_in,
                              void* d_out, int out_size) {
    const float* inputs = (const float*)d_in[0];
    const float* states = (const float*)d_in[1];
    const float* qMax   = (const float*)d_in[2];
    const float* Ro     = (const float*)d_in[3];
    const float* Wp0    = (const float*)d_in[4];
    const float* bp0    = (const float*)d_in[5];
    const float* Wp2    = (const float*)d_in[6];
    const float* bp2    = (const float*)d_in[7];
    const float* Wp4    = (const float*)d_in[8];
    const float* bp4    = (const float*)d_in[9];
    const float* Wn     = (const float*)d_in[10];
    const float* bn     = (const float*)d_in[11];

    int n = in_sizes[0];  // B
    float* outV = (float*)d_out;
    float* outX = outV + n;

    // Primary: tiny table builder.
    build_mlp_table<<<TAB_N / THREADS, THREADS>>>(Wp0, bp0, Wp2, bp2, Wp4, bp4);

    // Secondary: main kernel, launched with programmatic dependent launch so it
    // overlaps the builder; it synchronizes in-kernel before reading the table.
    int blocks = (n + THREADS - 1) / THREADS;

    cudaLaunchConfig_t cfg = {};
    cfg.gridDim  = dim3(blocks, 1, 1);
    cfg.blockDim = dim3(THREADS, 1, 1);
    cfg.dynamicSmemBytes = 0;
    cfg.stream = 0;
    cudaLaunchAttribute attrs[1];
    attrs[0].id = cudaLaunchAttributeProgrammaticStreamSerialization;
    attrs[0].val.programmaticStreamSerializationAllowed = 1;
    cfg.attrs = attrs;
    cfg.numAttrs = 1;

    cudaLaunchKernelEx(&cfg, battery_cell_kernel,
                       inputs, states, qMax, Ro, Wn, bn, outV, outX, n);
}